// round 2
// baseline (speedup 1.0000x reference)
#include <cuda_runtime.h>
#include <math.h>

// ---------------- device scratch (no allocations allowed) ----------------
__device__ float g_LinvT[32 * 64 * 64];  // [k][e][d] = Linv_k[d][e]
__device__ float g_t[32 * 64];           // t_k = Linv_k * centroid_k
__device__ float g_nhc[32];              // -0.5*(D*log2pi + logdet_k)
__device__ float g_part[4096];           // per-block partial sums

#define LOG2PI 1.8378770664093453f

// ---------------- prep: Cholesky, logdet, triangular inverse ----------------
// grid = 32 (one block per component), block = 64 threads (one per row)
__global__ void __launch_bounds__(64) prep_kernel(const float* __restrict__ cov,
                                                  const float* __restrict__ centroid)
{
    __shared__ float A[64][65];   // cov -> L (lower)
    __shared__ float Li[64][65];  // L^{-1}
    __shared__ float dlog[64];

    const int k = blockIdx.x;
    const int i = threadIdx.x;

    // load cov[k] row i
    #pragma unroll 4
    for (int j = 0; j < 64; ++j) A[i][j] = cov[k * 4096 + i * 64 + j];
    __syncthreads();

    // left-looking Cholesky, thread i handles row i
    for (int j = 0; j < 64; ++j) {
        float s = 0.f;
        if (i >= j) {
            s = A[i][j];
            for (int m = 0; m < j; ++m) s -= A[i][m] * A[j][m];
            if (i == j) A[j][j] = sqrtf(s);
        }
        __syncthreads();
        if (i > j) A[i][j] = s / A[j][j];
        __syncthreads();
    }

    dlog[i] = 2.f * logf(A[i][i]);
    __syncthreads();
    if (i == 0) {
        float ld = 0.f;
        for (int m = 0; m < 64; ++m) ld += dlog[m];
        g_nhc[k] = -0.5f * (64.f * LOG2PI + ld);
    }

    // invert lower-triangular L: thread c = i solves L y = e_c (column c)
    {
        const int c = i;
        for (int r = 0; r < 64; ++r) {
            float v = 0.f;
            if (r >= c) {
                v = (r == c) ? 1.f : 0.f;
                for (int m = c; m < r; ++m) v -= A[r][m] * Li[m][c];
                v /= A[r][r];
            }
            Li[r][c] = v;   // zero above diagonal
        }
    }
    __syncthreads();

    // t_k[i] = sum_e Linv[i][e] * centroid[k][e]
    float tv = 0.f;
    for (int e = 0; e <= i; ++e) tv += Li[i][e] * centroid[k * 64 + e];
    g_t[k * 64 + i] = tv;

    // store transposed: g_LinvT[k][e][d] = Li[d][e]   (thread i = d, coalesced over d)
    #pragma unroll 4
    for (int e = 0; e < 64; ++e)
        g_LinvT[k * 4096 + e * 64 + i] = Li[i][e];
}

// ---------------- main: per-tile weighted quad accumulation ----------------
// grid = B/64, block = 128 threads
__global__ void __launch_bounds__(128) main_kernel(const float* __restrict__ emb,
                                                   const float* __restrict__ pi,
                                                   const int* __restrict__ labels)
{
    __shared__ float Xs[64][65];   // [e][b]  (padded: scattered writes)
    __shared__ float Ls[64][64];   // [e][d] = Linv[d][e]
    __shared__ float Ps[64][33];   // [b][k]  (padded)
    __shared__ float ts[64];
    __shared__ float nhc[32];
    __shared__ int   lbl[64];
    __shared__ float red[128];

    const int tid = threadIdx.x;
    const int b0  = blockIdx.x * 64;

    if (tid < 64) lbl[tid] = labels[b0 + tid];
    if (tid < 32) nhc[tid] = g_nhc[tid];
    __syncthreads();

    // gather embedding rows (transposed into Xs): e4 = tid%16, bsub = tid/16
    {
        const int e4 = tid & 15, bs = tid >> 4;
        #pragma unroll
        for (int it = 0; it < 8; ++it) {
            const int b = bs + it * 8;
            const float4 v = *(const float4*)(emb + (size_t)lbl[b] * 64 + e4 * 4);
            Xs[e4 * 4 + 0][b] = v.x;
            Xs[e4 * 4 + 1][b] = v.y;
            Xs[e4 * 4 + 2][b] = v.z;
            Xs[e4 * 4 + 3][b] = v.w;
        }
    }
    // gather pi rows: c4 = tid%8, bsub = tid/8
    {
        const int c4 = tid & 7, bs = tid >> 3;
        #pragma unroll
        for (int it = 0; it < 4; ++it) {
            const int b = bs + it * 16;
            const float4 v = *(const float4*)(pi + (size_t)lbl[b] * 32 + c4 * 4);
            Ps[b][c4 * 4 + 0] = v.x;
            Ps[b][c4 * 4 + 1] = v.y;
            Ps[b][c4 * 4 + 2] = v.z;
            Ps[b][c4 * 4 + 3] = v.w;
        }
    }

    const int w    = tid >> 5;          // warp 0..3
    const int lane = tid & 31;
    const int dx   = lane & 3;
    const int by   = lane >> 2;
    // permute d-range ownership per block so SMSPs get balanced triangular work
    const int w_eff = (w + (int)blockIdx.x) & 3;
    const int d0    = w_eff * 16 + dx * 4;
    const int e_end = w_eff * 16 + 16;  // Linv is lower-tri: z_d needs e <= d only

    float acc = 0.f;

    for (int k = 0; k < 32; ++k) {
        __syncthreads();  // protect Ls/ts reuse (also covers Xs/Ps writes on k==0)
        {
            const float4* src = (const float4*)(g_LinvT + k * 4096);
            float4*       dst = (float4*)(&Ls[0][0]);
            #pragma unroll
            for (int i = tid; i < 1024; i += 128) dst[i] = src[i];
            if (tid < 64) ts[tid] = g_t[k * 64 + tid];
        }
        __syncthreads();

        const float t0 = ts[d0], t1 = ts[d0 + 1], t2 = ts[d0 + 2], t3 = ts[d0 + 3];
        float z0[8], z1[8], z2[8], z3[8];
        #pragma unroll
        for (int i = 0; i < 8; ++i) { z0[i] = -t0; z1[i] = -t1; z2[i] = -t2; z3[i] = -t3; }

        #pragma unroll 4
        for (int e = 0; e < e_end; ++e) {
            const float l0 = Ls[e][d0];
            const float l1 = Ls[e][d0 + 1];
            const float l2 = Ls[e][d0 + 2];
            const float l3 = Ls[e][d0 + 3];
            #pragma unroll
            for (int i = 0; i < 8; ++i) {
                const float x = Xs[e][i * 8 + by];
                z0[i] = fmaf(x, l0, z0[i]);
                z1[i] = fmaf(x, l1, z1[i]);
                z2[i] = fmaf(x, l2, z2[i]);
                z3[i] = fmaf(x, l3, z3[i]);
            }
        }

        #pragma unroll
        for (int i = 0; i < 8; ++i) {
            const int b = i * 8 + by;
            float q = z0[i] * z0[i];
            q = fmaf(z1[i], z1[i], q);
            q = fmaf(z2[i], z2[i], q);
            q = fmaf(z3[i], z3[i], q);
            acc = fmaf(Ps[b][k], q, acc);   // partial quad (over this thread's 4 d's)
        }
    }
    acc *= -0.5f;

    // constant + logdet part: sum_k Ps[b][k] * nhc[k], one thread per b
    if (tid < 64) {
        float c = 0.f;
        #pragma unroll
        for (int k = 0; k < 32; ++k) c = fmaf(Ps[tid][k], nhc[k], c);
        acc += c;
    }

    // deterministic block reduction
    red[tid] = acc;
    __syncthreads();
    #pragma unroll
    for (int st = 64; st > 0; st >>= 1) {
        if (tid < st) red[tid] += red[tid + st];
        __syncthreads();
    }
    if (tid == 0) g_part[blockIdx.x] = red[0];
}

// ---------------- final reduce ----------------
__global__ void __launch_bounds__(1024) reduce_kernel(float* __restrict__ out, int nb)
{
    __shared__ float s[1024];
    const int t = threadIdx.x;
    float a = 0.f;
    for (int i = t; i < nb; i += 1024) a += g_part[i];
    s[t] = a;
    __syncthreads();
    #pragma unroll
    for (int st = 512; st > 0; st >>= 1) {
        if (t < st) s[t] += s[t + st];
        __syncthreads();
    }
    if (t == 0) out[0] = fabsf(s[0]);
}

// ---------------- launch ----------------
extern "C" void kernel_launch(void* const* d_in, const int* in_sizes, int n_in,
                              void* d_out, int out_size)
{
    const float* emb    = (const float*)d_in[0];   // (500000, 64)
    const float* cen    = (const float*)d_in[1];   // (32, 64)
    const float* cov    = (const float*)d_in[2];   // (32, 64, 64)
    const float* pi     = (const float*)d_in[3];   // (500000, 32)
    const int*   labels = (const int*)d_in[4];     // (B,)
    const int B  = in_sizes[4];
    const int nb = B / 64;

    prep_kernel<<<32, 64>>>(cov, cen);
    main_kernel<<<nb, 128>>>(emb, pi, labels);
    reduce_kernel<<<1, 1024>>>((float*)d_out, nb);
}

// round 3
// speedup vs baseline: 2.6976x; 2.6976x over previous
#include <cuda_runtime.h>
#include <cuda_bf16.h>
#include <math.h>

// ---------------- device scratch (no allocations allowed) ----------------
__device__ __nv_bfloat16 g_Wb[32 * 64 * 64]; // [k][d][e] = bf16(Linv_k[d][e])
__device__ float g_t[32 * 64];               // t_k = Linv_k * centroid_k (fp32!)
__device__ float g_nhc[32];                  // -0.5*(D*log2pi + logdet_k)
__device__ float g_part[4096];               // per-block partial sums

#define LOG2PI 1.8378770664093453f

// ---------------- prep: Cholesky, logdet, triangular inverse ----------------
// grid = 32 (one block per component), block = 64 threads (one per row/col)
__global__ void __launch_bounds__(64) prep_kernel(const float* __restrict__ cov,
                                                  const float* __restrict__ centroid)
{
    __shared__ float A[64][65];   // cov -> L (lower)
    __shared__ float Li[64][65];  // L^{-1}
    __shared__ float dlog[64];

    const int k = blockIdx.x;
    const int i = threadIdx.x;

    #pragma unroll 4
    for (int j = 0; j < 64; ++j) A[i][j] = cov[k * 4096 + i * 64 + j];
    __syncthreads();

    // left-looking Cholesky, thread i handles row i; 4-way ILP on the dot
    for (int j = 0; j < 64; ++j) {
        float s = 0.f;
        if (i >= j) {
            float s0 = A[i][j], s1 = 0.f, s2 = 0.f, s3 = 0.f;
            int m = 0;
            for (; m + 3 < j; m += 4) {
                s0 -= A[i][m]     * A[j][m];
                s1 -= A[i][m + 1] * A[j][m + 1];
                s2 -= A[i][m + 2] * A[j][m + 2];
                s3 -= A[i][m + 3] * A[j][m + 3];
            }
            for (; m < j; ++m) s0 -= A[i][m] * A[j][m];
            s = (s0 + s1) + (s2 + s3);
            if (i == j) A[j][j] = sqrtf(s);
        }
        __syncthreads();
        if (i > j) A[i][j] = s / A[j][j];
        __syncthreads();
    }

    dlog[i] = 2.f * logf(A[i][i]);
    __syncthreads();
    if (i == 0) {
        float ld = 0.f;
        for (int m = 0; m < 64; ++m) ld += dlog[m];
        g_nhc[k] = -0.5f * (64.f * LOG2PI + ld);
    }

    // invert lower-triangular L: thread c solves L y = e_c; 4-way ILP inner
    {
        const int c = i;
        for (int r = 0; r < 64; ++r) {
            float v = 0.f;
            if (r >= c) {
                float v0 = (r == c) ? 1.f : 0.f, v1 = 0.f, v2 = 0.f, v3 = 0.f;
                int m = c;
                for (; m + 3 < r; m += 4) {
                    v0 -= A[r][m]     * Li[m][c];
                    v1 -= A[r][m + 1] * Li[m + 1][c];
                    v2 -= A[r][m + 2] * Li[m + 2][c];
                    v3 -= A[r][m + 3] * Li[m + 3][c];
                }
                for (; m < r; ++m) v0 -= A[r][m] * Li[m][c];
                v = ((v0 + v1) + (v2 + v3)) / A[r][r];
            }
            Li[r][c] = v;   // zero above diagonal
        }
    }
    __syncthreads();

    // t_k[i] = sum_e Linv[i][e] * centroid[k][e]   (fp32, exact shift)
    float tv = 0.f;
    for (int e = 0; e <= i; ++e) tv += Li[i][e] * centroid[k * 64 + e];
    g_t[k * 64 + i] = tv;

    // W in bf16, row d = i: Wb[k][d][e]
    #pragma unroll 4
    for (int e = 0; e < 64; ++e)
        g_Wb[k * 4096 + i * 64 + e] = __float2bfloat16_rn(Li[i][e]);
}

// ---------------- main: fused GEMM (bf16 HMMA) + square + weight ----------------
// grid = B/128, block = 256 threads (8 warps, each owns 16 batch rows)
#define SW 72   // bf16 smem row stride (144B): conflict-free fragment LDS

__global__ void __launch_bounds__(256) main_kernel(const float* __restrict__ emb,
                                                   const float* __restrict__ pi,
                                                   const int* __restrict__ labels)
{
    __shared__ __nv_bfloat16 Xs[128 * SW];   // [row][e]
    __shared__ __nv_bfloat16 Ws[64 * SW];    // [d][e] for current k
    __shared__ float Ps[128 * 33];           // [row][k]
    __shared__ float ts[64];                 // t for current k
    __shared__ float nhc[32];
    __shared__ int   lbl[128];
    __shared__ float red[256];

    const int tid = threadIdx.x;
    const int b0  = blockIdx.x * 128;

    if (tid < 128) lbl[tid] = labels[b0 + tid];
    if (tid < 32)  nhc[tid] = g_nhc[tid];
    __syncthreads();

    // gather embedding rows -> bf16 Xs
    {
        const int f4 = tid & 15, rg = tid >> 4;     // 16 float4/row, 16 rows/pass
        #pragma unroll
        for (int it = 0; it < 8; ++it) {
            const int row = rg + it * 16;
            const float4 v = *(const float4*)(emb + (size_t)lbl[row] * 64 + f4 * 4);
            __nv_bfloat162* p = (__nv_bfloat162*)&Xs[row * SW + f4 * 4];
            p[0] = __nv_bfloat162(__float2bfloat16_rn(v.x), __float2bfloat16_rn(v.y));
            p[1] = __nv_bfloat162(__float2bfloat16_rn(v.z), __float2bfloat16_rn(v.w));
        }
    }
    // gather pi rows
    {
        const int f4 = tid & 7, rg = tid >> 3;      // 8 float4/row, 32 rows/pass
        #pragma unroll
        for (int it = 0; it < 4; ++it) {
            const int row = rg + it * 32;
            const float4 v = *(const float4*)(pi + (size_t)lbl[row] * 32 + f4 * 4);
            Ps[row * 33 + f4 * 4 + 0] = v.x;
            Ps[row * 33 + f4 * 4 + 1] = v.y;
            Ps[row * 33 + f4 * 4 + 2] = v.z;
            Ps[row * 33 + f4 * 4 + 3] = v.w;
        }
    }

    const int w    = tid >> 5;        // warp 0..7 -> rows w*16 .. w*16+15
    const int lane = tid & 31;
    const int g    = lane >> 2;       // groupID 0..7
    const int t4   = lane & 3;        // thread in group
    const int rowA = w * 16 + g;      // fragment rows rowA, rowA+8

    float acc = 0.f;

    for (int k = 0; k < 32; ++k) {
        __syncthreads();   // previous k's reads done; also guards gather on k==0
        // cooperative load W_k (dense) -> Ws (padded)
        {
            const uint4* src = (const uint4*)(g_Wb + k * 4096);  // 512 uint4
            #pragma unroll
            for (int it = 0; it < 2; ++it) {
                const int i = tid + it * 256;
                const int row = i >> 3, c8 = i & 7;
                *(uint4*)&Ws[row * SW + c8 * 8] = src[i];
            }
            if (tid < 64) ts[tid] = g_t[k * 64 + tid];
        }
        __syncthreads();

        // preload A fragments for the 4 e-steps (reused across all 8 n-tiles)
        unsigned a0[4], a1[4], a2[4], a3[4];
        #pragma unroll
        for (int es = 0; es < 4; ++es) {
            const int e0 = es * 16 + 2 * t4;
            a0[es] = *(const unsigned*)&Xs[(rowA)     * SW + e0];
            a1[es] = *(const unsigned*)&Xs[(rowA + 8) * SW + e0];
            a2[es] = *(const unsigned*)&Xs[(rowA)     * SW + e0 + 8];
            a3[es] = *(const unsigned*)&Xs[(rowA + 8) * SW + e0 + 8];
        }

        const float pg  = Ps[rowA * 33 + k];
        const float pg8 = Ps[(rowA + 8) * 33 + k];

        #pragma unroll
        for (int j = 0; j < 8; ++j) {            // n-tiles: d = j*8 .. j*8+7
            float c0 = -ts[j * 8 + 2 * t4];
            float c1 = -ts[j * 8 + 2 * t4 + 1];
            float c2 = c0, c3 = c1;
            #pragma unroll
            for (int es = 0; es < 4; ++es) {
                const int e0 = es * 16 + 2 * t4;
                const unsigned b0 = *(const unsigned*)&Ws[(j * 8 + g) * SW + e0];
                const unsigned b1 = *(const unsigned*)&Ws[(j * 8 + g) * SW + e0 + 8];
                asm volatile(
                    "mma.sync.aligned.m16n8k16.row.col.f32.bf16.bf16.f32 "
                    "{%0,%1,%2,%3}, {%4,%5,%6,%7}, {%8,%9}, {%0,%1,%2,%3};\n"
                    : "+f"(c0), "+f"(c1), "+f"(c2), "+f"(c3)
                    : "r"(a0[es]), "r"(a1[es]), "r"(a2[es]), "r"(a3[es]),
                      "r"(b0), "r"(b1));
            }
            const float s0 = fmaf(c0, c0, c1 * c1);   // row rowA
            const float s1 = fmaf(c2, c2, c3 * c3);   // row rowA+8
            acc = fmaf(pg,  s0, acc);
            acc = fmaf(pg8, s1, acc);
        }
    }
    acc *= -0.5f;

    // constant + logdet part: one thread per batch row
    if (tid < 128) {
        float c = 0.f;
        #pragma unroll
        for (int k = 0; k < 32; ++k) c = fmaf(Ps[tid * 33 + k], nhc[k], c);
        acc += c;
    }

    // deterministic block reduction
    red[tid] = acc;
    __syncthreads();
    #pragma unroll
    for (int st = 128; st > 0; st >>= 1) {
        if (tid < st) red[tid] += red[tid + st];
        __syncthreads();
    }
    if (tid == 0) g_part[blockIdx.x] = red[0];
}

// ---------------- final reduce ----------------
__global__ void __launch_bounds__(1024) reduce_kernel(float* __restrict__ out, int nb)
{
    __shared__ float s[1024];
    const int t = threadIdx.x;
    float a = 0.f;
    for (int i = t; i < nb; i += 1024) a += g_part[i];
    s[t] = a;
    __syncthreads();
    #pragma unroll
    for (int st = 512; st > 0; st >>= 1) {
        if (t < st) s[t] += s[t + st];
        __syncthreads();
    }
    if (t == 0) out[0] = fabsf(s[0]);
}

// ---------------- launch ----------------
extern "C" void kernel_launch(void* const* d_in, const int* in_sizes, int n_in,
                              void* d_out, int out_size)
{
    const float* emb    = (const float*)d_in[0];   // (500000, 64)
    const float* cen    = (const float*)d_in[1];   // (32, 64)
    const float* cov    = (const float*)d_in[2];   // (32, 64, 64)
    const float* pi     = (const float*)d_in[3];   // (500000, 32)
    const int*   labels = (const int*)d_in[4];     // (B,)
    const int B  = in_sizes[4];
    const int nb = B / 128;

    prep_kernel<<<32, 64>>>(cov, cen);
    main_kernel<<<nb, 256>>>(emb, pi, labels);
    reduce_kernel<<<1, 1024>>>((float*)d_out, nb);
}

// round 4
// speedup vs baseline: 3.1032x; 1.1503x over previous
#include <cuda_runtime.h>
#include <cuda_bf16.h>
#include <math.h>

// ---------------- device scratch (no allocations allowed) ----------------
__device__ float         g_L[32 * 64 * 64];   // Cholesky factor L (lower, row-major)
__device__ __nv_bfloat16 g_Wb[32 * 64 * 64];  // [k][d][e] = bf16(Linv_k[d][e])
__device__ float g_t[32 * 64];                // t_k = Linv_k * centroid_k (fp32)
__device__ float g_nhc[32];                   // -0.5*(D*log2pi + logdet_k)
__device__ float g_part[4096];                // per-block partial sums

#define LOG2PI 1.8378770664093453f

// ---------------- fused prep: Cholesky + warp-parallel triangular inverse ----
// grid = 32 (one block per component), block = 256 threads
__global__ void __launch_bounds__(256) prep_kernel(const float* __restrict__ cov,
                                                   const float* __restrict__ cen)
{
    __shared__ float A[64 * 65];    // cov -> L (lower)
    __shared__ float Li[64 * 65];   // L^{-1}
    __shared__ float rd[64];        // 1 / L[m][m]
    __shared__ float dlog[64];

    const int k   = blockIdx.x;
    const int tid = threadIdx.x;
    const int i   = tid;            // row index for Cholesky phase (i < 64 active)

    // load cov[k]
    for (int idx = tid; idx < 4096; idx += 256)
        A[(idx >> 6) * 65 + (idx & 63)] = cov[k * 4096 + idx];
    __syncthreads();

    // right-looking Cholesky: thread i owns row i (threads >=64 just barrier)
    for (int j = 0; j < 64; ++j) {
        const float d  = A[j * 65 + j];
        float rs = rsqrtf(d);
        rs = rs * (1.5f - 0.5f * d * rs * rs);   // Newton: full fp32 accuracy
        float lij = 0.f;
        if (i < 64 && i >= j) {
            lij = A[i * 65 + j] * rs;            // diag: d*rs = sqrt(d)
            A[i * 65 + j] = lij;
        }
        __syncthreads();
        if (i < 64 && i > j) {
            #pragma unroll 4
            for (int m = j + 1; m <= i; ++m)
                A[i * 65 + m] -= lij * A[m * 65 + j];   // A[m][j] broadcast
        }
        __syncthreads();
    }

    if (tid < 64) {
        dlog[tid] = 2.f * logf(A[tid * 65 + tid]);
        rd[tid]   = 1.0f / A[tid * 65 + tid];
    }
    __syncthreads();
    if (tid == 0) {
        float ld = 0.f;
        #pragma unroll 4
        for (int m = 0; m < 64; ++m) ld += dlog[m];
        g_nhc[k] = -0.5f * (64.f * LOG2PI + ld);
    }

    // warp-parallel forward substitution: warp w solves columns w*8 .. w*8+7.
    // lane l owns rows l and l+32; 8 columns in flight per warp (ILP hides shfl).
    {
        const int w = tid >> 5, l = tid & 31;
        const int r0 = l, r1 = l + 32;
        const int c0 = w * 8;
        float v0[8], v1[8];
        #pragma unroll
        for (int j = 0; j < 8; ++j) {
            v0[j] = (r0 == c0 + j) ? 1.f : 0.f;
            v1[j] = (r1 == c0 + j) ? 1.f : 0.f;
        }
        for (int m = 0; m < 64; ++m) {
            const float lr0 = (r0 > m) ? A[r0 * 65 + m] : 0.f;
            const float lr1 = (r1 > m) ? A[r1 * 65 + m] : 0.f;
            const float rdm = rd[m];
            const int   src = m & 31;
            const bool  lo  = (m < 32);
            #pragma unroll
            for (int j = 0; j < 8; ++j) {
                const float resid = lo ? v0[j] : v1[j];
                const float ym = __shfl_sync(0xffffffffu, resid, src) * rdm;
                v0[j] -= lr0 * ym;
                v1[j] -= lr1 * ym;
                if (l == src) Li[m * 65 + c0 + j] = ym;
            }
        }
    }
    __syncthreads();

    // t_k[i] = sum_e Li[i][e] * cen[k][e]  (fp32 exact shift)
    if (tid < 64) {
        float tv = 0.f;
        #pragma unroll 4
        for (int e = 0; e <= tid; ++e) tv += Li[tid * 65 + e] * cen[k * 64 + e];
        g_t[k * 64 + tid] = tv;
    }
    // store L (for reference/debug path of nothing else) and bf16 W
    for (int idx = tid; idx < 4096; idx += 256) {
        const int d = idx >> 6, e = idx & 63;
        const float v = (e <= d) ? Li[d * 65 + e] : 0.f;
        g_Wb[k * 4096 + idx] = __float2bfloat16_rn(v);
    }
}

// ---------------- main: fused GEMM (bf16 HMMA) + square + weight ----------------
// grid = B/256, block = 256 threads (8 warps, each owns 32 batch rows)
#define SW 72   // bf16 smem row stride (144B): conflict-free fragment LDS

// dynamic smem layout (bytes)
#define OFF_XS   0                         // bf16 [256*SW]           36864
#define OFF_WS   36864                     // bf16 [2][64*SW]         18432
#define OFF_PS   55296                     // float [256*33]          33792
#define OFF_TS   89088                     // float [2][64]             512
#define OFF_NHC  89600                     // float [32]                128
#define OFF_LBL  89728                     // int   [256]              1024
#define OFF_RED  90752                     // float [256]              1024
#define SMEM_TOTAL 91776

__device__ __forceinline__ void cp_async16(void* dst, const void* src) {
    unsigned a = (unsigned)__cvta_generic_to_shared(dst);
    asm volatile("cp.async.ca.shared.global [%0], [%1], 16;\n" :: "r"(a), "l"(src));
}

__global__ void __launch_bounds__(256, 2) main_kernel(const float* __restrict__ emb,
                                                      const float* __restrict__ pi,
                                                      const int* __restrict__ labels)
{
    extern __shared__ char smem[];
    __nv_bfloat16* Xs  = (__nv_bfloat16*)(smem + OFF_XS);
    __nv_bfloat16* Ws  = (__nv_bfloat16*)(smem + OFF_WS);   // [buf][64*SW]
    float* Ps  = (float*)(smem + OFF_PS);
    float* ts  = (float*)(smem + OFF_TS);                    // [buf][64]
    float* nhc = (float*)(smem + OFF_NHC);
    int*   lbl = (int*)  (smem + OFF_LBL);
    float* red = (float*)(smem + OFF_RED);

    const int tid = threadIdx.x;
    const int b0  = blockIdx.x * 256;

    lbl[tid] = labels[b0 + tid];
    if (tid < 32) nhc[tid] = g_nhc[tid];
    __syncthreads();

    // gather embedding rows -> bf16 Xs
    {
        const int f4 = tid & 15, rg = tid >> 4;     // 16 float4/row, 16 rows/pass
        #pragma unroll
        for (int it = 0; it < 16; ++it) {
            const int row = rg + it * 16;
            const float4 v = *(const float4*)(emb + (size_t)lbl[row] * 64 + f4 * 4);
            __nv_bfloat162* p = (__nv_bfloat162*)&Xs[row * SW + f4 * 4];
            p[0] = __nv_bfloat162(__float2bfloat16_rn(v.x), __float2bfloat16_rn(v.y));
            p[1] = __nv_bfloat162(__float2bfloat16_rn(v.z), __float2bfloat16_rn(v.w));
        }
    }
    // gather pi rows
    {
        const int f4 = tid & 7, rg = tid >> 3;      // 8 float4/row, 32 rows/pass
        #pragma unroll
        for (int it = 0; it < 8; ++it) {
            const int row = rg + it * 32;
            const float4 v = *(const float4*)(pi + (size_t)lbl[row] * 32 + f4 * 4);
            Ps[row * 33 + f4 * 4 + 0] = v.x;
            Ps[row * 33 + f4 * 4 + 1] = v.y;
            Ps[row * 33 + f4 * 4 + 2] = v.z;
            Ps[row * 33 + f4 * 4 + 3] = v.w;
        }
    }

    const int w    = tid >> 5;        // warp 0..7 -> rows w*32 .. w*32+31
    const int lane = tid & 31;
    const int g    = lane >> 2;       // groupID 0..7
    const int t4   = lane & 3;
    const int rowA = w * 32 + g;      // fragment rows rowA(+8) and rowA+16(+24)

    // W / t prefetch (cp.async) into buffer b: 512+16 x 16B by 256 threads
    auto prefetch = [&](int k, int b) {
        const uint4* src = (const uint4*)(g_Wb + k * 4096);
        #pragma unroll
        for (int it = 0; it < 2; ++it) {
            const int idx = tid + it * 256;
            cp_async16(&Ws[b * 64 * SW + (idx >> 3) * SW + (idx & 7) * 8], &src[idx]);
        }
        if (tid < 16) cp_async16(&ts[b * 64 + tid * 4], &g_t[k * 64 + tid * 4]);
    };

    prefetch(0, 0);
    asm volatile("cp.async.commit_group;\n");

    float acc = 0.f;

    for (int k = 0; k < 32; ++k) {
        const int buf = k & 1;
        __syncthreads();                           // prior compute's reads done
        if (k + 1 < 32) prefetch(k + 1, buf ^ 1);
        asm volatile("cp.async.commit_group;\n");
        asm volatile("cp.async.wait_group 1;\n");  // buffer `buf` ready
        __syncthreads();

        const __nv_bfloat16* Wk = Ws + buf * 64 * SW;
        const float*        tsb = ts + buf * 64;

        // A fragments for both row-groups (reused across all j)
        unsigned aA[4][4], aB[4][4];
        #pragma unroll
        for (int es = 0; es < 4; ++es) {
            const int e0 = es * 16 + 2 * t4;
            aA[es][0] = *(const unsigned*)&Xs[(rowA)      * SW + e0];
            aA[es][1] = *(const unsigned*)&Xs[(rowA +  8) * SW + e0];
            aA[es][2] = *(const unsigned*)&Xs[(rowA)      * SW + e0 + 8];
            aA[es][3] = *(const unsigned*)&Xs[(rowA +  8) * SW + e0 + 8];
            aB[es][0] = *(const unsigned*)&Xs[(rowA + 16) * SW + e0];
            aB[es][1] = *(const unsigned*)&Xs[(rowA + 24) * SW + e0];
            aB[es][2] = *(const unsigned*)&Xs[(rowA + 16) * SW + e0 + 8];
            aB[es][3] = *(const unsigned*)&Xs[(rowA + 24) * SW + e0 + 8];
        }
        const float pA0 = Ps[(rowA)      * 33 + k];
        const float pA8 = Ps[(rowA +  8) * 33 + k];
        const float pB0 = Ps[(rowA + 16) * 33 + k];
        const float pB8 = Ps[(rowA + 24) * 33 + k];

        #pragma unroll
        for (int j = 0; j < 8; ++j) {              // n-tiles: d = j*8 .. j*8+7
            const float t0 = tsb[j * 8 + 2 * t4];
            const float t1 = tsb[j * 8 + 2 * t4 + 1];
            float cA0 = -t0, cA1 = -t1, cA2 = -t0, cA3 = -t1;
            float cB0 = -t0, cB1 = -t1, cB2 = -t0, cB3 = -t1;
            #pragma unroll
            for (int es = 0; es < 4; ++es) {
                const int e0 = es * 16 + 2 * t4;
                const unsigned b0 = *(const unsigned*)&Wk[(j * 8 + g) * SW + e0];
                const unsigned b1 = *(const unsigned*)&Wk[(j * 8 + g) * SW + e0 + 8];
                asm volatile(
                    "mma.sync.aligned.m16n8k16.row.col.f32.bf16.bf16.f32 "
                    "{%0,%1,%2,%3}, {%4,%5,%6,%7}, {%8,%9}, {%0,%1,%2,%3};\n"
                    : "+f"(cA0), "+f"(cA1), "+f"(cA2), "+f"(cA3)
                    : "r"(aA[es][0]), "r"(aA[es][1]), "r"(aA[es][2]), "r"(aA[es][3]),
                      "r"(b0), "r"(b1));
                asm volatile(
                    "mma.sync.aligned.m16n8k16.row.col.f32.bf16.bf16.f32 "
                    "{%0,%1,%2,%3}, {%4,%5,%6,%7}, {%8,%9}, {%0,%1,%2,%3};\n"
                    : "+f"(cB0), "+f"(cB1), "+f"(cB2), "+f"(cB3)
                    : "r"(aB[es][0]), "r"(aB[es][1]), "r"(aB[es][2]), "r"(aB[es][3]),
                      "r"(b0), "r"(b1));
            }
            acc = fmaf(pA0, fmaf(cA0, cA0, cA1 * cA1), acc);
            acc = fmaf(pA8, fmaf(cA2, cA2, cA3 * cA3), acc);
            acc = fmaf(pB0, fmaf(cB0, cB0, cB1 * cB1), acc);
            acc = fmaf(pB8, fmaf(cB2, cB2, cB3 * cB3), acc);
        }
    }
    acc *= -0.5f;

    // constant + logdet part: one thread per batch row
    {
        float c = 0.f;
        #pragma unroll
        for (int kk = 0; kk < 32; ++kk) c = fmaf(Ps[tid * 33 + kk], nhc[kk], c);
        acc += c;
    }

    // deterministic block reduction
    red[tid] = acc;
    __syncthreads();
    #pragma unroll
    for (int st = 128; st > 0; st >>= 1) {
        if (tid < st) red[tid] += red[tid + st];
        __syncthreads();
    }
    if (tid == 0) g_part[blockIdx.x] = red[0];
}

// ---------------- final reduce ----------------
__global__ void __launch_bounds__(1024) reduce_kernel(float* __restrict__ out, int nb)
{
    __shared__ float s[1024];
    const int t = threadIdx.x;
    float a = 0.f;
    for (int i = t; i < nb; i += 1024) a += g_part[i];
    s[t] = a;
    __syncthreads();
    #pragma unroll
    for (int st = 512; st > 0; st >>= 1) {
        if (t < st) s[t] += s[t + st];
        __syncthreads();
    }
    if (t == 0) out[0] = fabsf(s[0]);
}

// ---------------- launch ----------------
extern "C" void kernel_launch(void* const* d_in, const int* in_sizes, int n_in,
                              void* d_out, int out_size)
{
    const float* emb    = (const float*)d_in[0];   // (500000, 64)
    const float* cen    = (const float*)d_in[1];   // (32, 64)
    const float* cov    = (const float*)d_in[2];   // (32, 64, 64)
    const float* pi     = (const float*)d_in[3];   // (500000, 32)
    const int*   labels = (const int*)d_in[4];     // (B,)
    const int B  = in_sizes[4];
    const int nb = B / 256;

    static int configured = 0;
    if (!configured) {
        cudaFuncSetAttribute(main_kernel, cudaFuncAttributeMaxDynamicSharedMemorySize,
                             SMEM_TOTAL);
        configured = 1;
    }

    prep_kernel<<<32, 256>>>(cov, cen);
    main_kernel<<<nb, 256, SMEM_TOTAL>>>(emb, pi, labels);
    reduce_kernel<<<1, 1024>>>((float*)d_out, nb);
}

// round 5
// speedup vs baseline: 4.7311x; 1.5246x over previous
#include <cuda_runtime.h>
#include <cuda_bf16.h>
#include <math.h>

// ---------------- device scratch (no allocations allowed) ----------------
__device__ __nv_bfloat16 g_Wb[32 * 64 * 64];  // [k][d][e] = bf16(Linv_k[d][e])
__device__ float g_t[32 * 64];                // t_k = Linv_k * centroid_k (fp32)
__device__ float g_nhc[32];                   // -0.5*(D*log2pi + logdet_k)
__device__ float g_part[4096];                // per-block partial sums

#define LOG2PI 1.8378770664093453f

// ---------------- prep: blocked-panel Cholesky + warp-parallel inverse -------
// grid = 32 (one block per component), block = 256 threads
__global__ void __launch_bounds__(256) prep_kernel(const float* __restrict__ cov,
                                                   const float* __restrict__ cen)
{
    __shared__ float A[64 * 65];    // cov -> L (lower); upper = symmetric junk
    __shared__ float Li[64 * 65];   // L^{-1}
    __shared__ float rd[64];        // 1 / L[m][m]
    __shared__ float dlog[64];

    const int k   = blockIdx.x;
    const int tid = threadIdx.x;
    const int l   = tid & 31;

    // load cov[k]
    for (int idx = tid; idx < 4096; idx += 256)
        A[(idx >> 6) * 65 + (idx & 63)] = cov[k * 4096 + idx];
    __syncthreads();

    // ---- blocked right-looking Cholesky: 8 panels of 8 columns ----
    #pragma unroll 1
    for (int p = 0; p < 8; ++p) {
        const int c0 = p * 8;

        // panel factorization: warp 0 only, fully register-resident
        if (tid < 32) {
            const int r0 = c0 + l;
            const int r1 = c0 + 32 + l;
            const bool act0 = (r0 < 64);
            const bool act1 = (r1 < 64);
            float a0[8], a1[8];
            #pragma unroll
            for (int m = 0; m < 8; ++m) {
                a0[m] = act0 ? A[r0 * 65 + c0 + m] : 0.f;
                a1[m] = act1 ? A[r1 * 65 + c0 + m] : 0.f;
            }
            #pragma unroll
            for (int jj = 0; jj < 8; ++jj) {
                // pivot diagonal (lane jj holds row c0+jj)
                const float d = __shfl_sync(0xffffffffu, a0[jj], jj);
                float rs = rsqrtf(d);
                rs = rs * (1.5f - 0.5f * d * rs * rs);   // Newton: fp32 accuracy
                // scale column jj (pivot lane gets sqrt(d))
                if (act0 && l >= jj) a0[jj] *= rs;
                if (act1)            a1[jj] *= rs;
                // multipliers L[c0+m][c0+jj] live in lane m's a0[jj]
                float lv[8];
                #pragma unroll
                for (int m = jj + 1; m < 8; ++m)
                    lv[m] = __shfl_sync(0xffffffffu, a0[jj], m);
                // rank-1 update restricted to panel columns
                #pragma unroll
                for (int m = jj + 1; m < 8; ++m) {
                    if (act0 && l > jj) a0[m] -= a0[jj] * lv[m];
                    if (act1)           a1[m] -= a1[jj] * lv[m];
                }
            }
            #pragma unroll
            for (int m = 0; m < 8; ++m) {
                if (act0) A[r0 * 65 + c0 + m] = a0[m];
                if (act1) A[r1 * 65 + c0 + m] = a1[m];
            }
        }
        __syncthreads();

        // trailing rank-8 update: rows/cols in [c0+8, 64), all 256 threads.
        // full square kept (upper = symmetric copies, preserves symmetry).
        const int R = 56 - c0;
        if (R > 0) {
            const int rr = tid >> 2;
            const int cq = tid & 3;
            if (rr < R) {
                const int r = c0 + 8 + rr;
                float pr[8];
                #pragma unroll
                for (int m = 0; m < 8; ++m) pr[m] = A[r * 65 + c0 + m];
                for (int cc = cq; cc < R; cc += 4) {
                    const int c = c0 + 8 + cc;
                    float s = A[r * 65 + c];
                    #pragma unroll
                    for (int m = 0; m < 8; ++m) s -= pr[m] * A[c * 65 + c0 + m];
                    A[r * 65 + c] = s;
                }
            }
        }
        __syncthreads();
    }

    if (tid < 64) {
        const float dii = A[tid * 65 + tid];
        dlog[tid] = 2.f * logf(dii);
        rd[tid]   = 1.0f / dii;
    }
    __syncthreads();
    if (tid == 0) {
        float ld = 0.f;
        #pragma unroll 4
        for (int m = 0; m < 64; ++m) ld += dlog[m];
        g_nhc[k] = -0.5f * (64.f * LOG2PI + ld);
    }

    // warp-parallel forward substitution: warp w solves columns w*8 .. w*8+7.
    // lane l owns rows l and l+32; 8 columns in flight per warp.
    {
        const int w = tid >> 5;
        const int r0 = l, r1 = l + 32;
        const int c0 = w * 8;
        float v0[8], v1[8];
        #pragma unroll
        for (int j = 0; j < 8; ++j) {
            v0[j] = (r0 == c0 + j) ? 1.f : 0.f;
            v1[j] = (r1 == c0 + j) ? 1.f : 0.f;
        }
        for (int m = 0; m < 64; ++m) {
            const float lr0 = (r0 > m) ? A[r0 * 65 + m] : 0.f;
            const float lr1 = (r1 > m) ? A[r1 * 65 + m] : 0.f;
            const float rdm = rd[m];
            const int   src = m & 31;
            const bool  lo  = (m < 32);
            #pragma unroll
            for (int j = 0; j < 8; ++j) {
                const float resid = lo ? v0[j] : v1[j];
                const float ym = __shfl_sync(0xffffffffu, resid, src) * rdm;
                v0[j] -= lr0 * ym;
                v1[j] -= lr1 * ym;
                if (l == src) Li[m * 65 + c0 + j] = ym;
            }
        }
    }
    __syncthreads();

    // t_k[i] = sum_e Li[i][e] * cen[k][e]  (fp32 exact shift)
    if (tid < 64) {
        float tv = 0.f;
        #pragma unroll 4
        for (int e = 0; e <= tid; ++e) tv += Li[tid * 65 + e] * cen[k * 64 + e];
        g_t[k * 64 + tid] = tv;
    }
    // bf16 W
    for (int idx = tid; idx < 4096; idx += 256) {
        const int d = idx >> 6, e = idx & 63;
        const float v = (e <= d) ? Li[d * 65 + e] : 0.f;
        g_Wb[k * 4096 + idx] = __float2bfloat16_rn(v);
    }
}

// ---------------- main: fused GEMM (bf16 HMMA) + square + weight ----------------
// grid = B/256, block = 256 threads (8 warps, each owns 32 batch rows)
#define SW 72   // bf16 smem row stride (144B): conflict-free fragment LDS

// dynamic smem layout (bytes)
#define OFF_XS   0                         // bf16 [256*SW]           36864
#define OFF_WS   36864                     // bf16 [2][64*SW]         18432
#define OFF_PS   55296                     // float [256*33]          33792
#define OFF_TS   89088                     // float [2][64]             512
#define OFF_NHC  89600                     // float [32]                128
#define OFF_LBL  89728                     // int   [256]              1024
#define OFF_RED  90752                     // float [256]              1024
#define SMEM_TOTAL 91776

__device__ __forceinline__ void cp_async16(void* dst, const void* src) {
    unsigned a = (unsigned)__cvta_generic_to_shared(dst);
    asm volatile("cp.async.ca.shared.global [%0], [%1], 16;\n" :: "r"(a), "l"(src));
}

__global__ void __launch_bounds__(256, 2) main_kernel(const float* __restrict__ emb,
                                                      const float* __restrict__ pi,
                                                      const int* __restrict__ labels)
{
    extern __shared__ char smem[];
    __nv_bfloat16* Xs  = (__nv_bfloat16*)(smem + OFF_XS);
    __nv_bfloat16* Ws  = (__nv_bfloat16*)(smem + OFF_WS);   // [buf][64*SW]
    float* Ps  = (float*)(smem + OFF_PS);
    float* ts  = (float*)(smem + OFF_TS);                    // [buf][64]
    float* nhc = (float*)(smem + OFF_NHC);
    int*   lbl = (int*)  (smem + OFF_LBL);
    float* red = (float*)(smem + OFF_RED);

    const int tid = threadIdx.x;
    const int b0  = blockIdx.x * 256;

    lbl[tid] = labels[b0 + tid];
    if (tid < 32) nhc[tid] = g_nhc[tid];
    __syncthreads();

    // gather embedding rows -> bf16 Xs
    {
        const int f4 = tid & 15, rg = tid >> 4;     // 16 float4/row, 16 rows/pass
        #pragma unroll
        for (int it = 0; it < 16; ++it) {
            const int row = rg + it * 16;
            const float4 v = *(const float4*)(emb + (size_t)lbl[row] * 64 + f4 * 4);
            __nv_bfloat162* p = (__nv_bfloat162*)&Xs[row * SW + f4 * 4];
            p[0] = __nv_bfloat162(__float2bfloat16_rn(v.x), __float2bfloat16_rn(v.y));
            p[1] = __nv_bfloat162(__float2bfloat16_rn(v.z), __float2bfloat16_rn(v.w));
        }
    }
    // gather pi rows
    {
        const int f4 = tid & 7, rg = tid >> 3;      // 8 float4/row, 32 rows/pass
        #pragma unroll
        for (int it = 0; it < 8; ++it) {
            const int row = rg + it * 32;
            const float4 v = *(const float4*)(pi + (size_t)lbl[row] * 32 + f4 * 4);
            Ps[row * 33 + f4 * 4 + 0] = v.x;
            Ps[row * 33 + f4 * 4 + 1] = v.y;
            Ps[row * 33 + f4 * 4 + 2] = v.z;
            Ps[row * 33 + f4 * 4 + 3] = v.w;
        }
    }

    const int w    = tid >> 5;        // warp 0..7 -> rows w*32 .. w*32+31
    const int lane = tid & 31;
    const int g    = lane >> 2;       // groupID 0..7
    const int t4   = lane & 3;
    const int rowA = w * 32 + g;      // fragment rows rowA(+8) and rowA+16(+24)

    // W / t prefetch (cp.async) into buffer b
    auto prefetch = [&](int k, int b) {
        const uint4* src = (const uint4*)(g_Wb + k * 4096);
        #pragma unroll
        for (int it = 0; it < 2; ++it) {
            const int idx = tid + it * 256;
            cp_async16(&Ws[b * 64 * SW + (idx >> 3) * SW + (idx & 7) * 8], &src[idx]);
        }
        if (tid < 16) cp_async16(&ts[b * 64 + tid * 4], &g_t[k * 64 + tid * 4]);
    };

    prefetch(0, 0);
    asm volatile("cp.async.commit_group;\n");

    float acc = 0.f;

    for (int k = 0; k < 32; ++k) {
        const int buf = k & 1;
        __syncthreads();                           // prior compute's reads done
        if (k + 1 < 32) prefetch(k + 1, buf ^ 1);
        asm volatile("cp.async.commit_group;\n");
        asm volatile("cp.async.wait_group 1;\n");  // buffer `buf` ready
        __syncthreads();

        const __nv_bfloat16* Wk = Ws + buf * 64 * SW;
        const float*        tsb = ts + buf * 64;

        // A fragments for both row-groups (reused across all j)
        unsigned aA[4][4], aB[4][4];
        #pragma unroll
        for (int es = 0; es < 4; ++es) {
            const int e0 = es * 16 + 2 * t4;
            aA[es][0] = *(const unsigned*)&Xs[(rowA)      * SW + e0];
            aA[es][1] = *(const unsigned*)&Xs[(rowA +  8) * SW + e0];
            aA[es][2] = *(const unsigned*)&Xs[(rowA)      * SW + e0 + 8];
            aA[es][3] = *(const unsigned*)&Xs[(rowA +  8) * SW + e0 + 8];
            aB[es][0] = *(const unsigned*)&Xs[(rowA + 16) * SW + e0];
            aB[es][1] = *(const unsigned*)&Xs[(rowA + 24) * SW + e0];
            aB[es][2] = *(const unsigned*)&Xs[(rowA + 16) * SW + e0 + 8];
            aB[es][3] = *(const unsigned*)&Xs[(rowA + 24) * SW + e0 + 8];
        }
        const float pA0 = Ps[(rowA)      * 33 + k];
        const float pA8 = Ps[(rowA +  8) * 33 + k];
        const float pB0 = Ps[(rowA + 16) * 33 + k];
        const float pB8 = Ps[(rowA + 24) * 33 + k];

        #pragma unroll
        for (int j = 0; j < 8; ++j) {              // n-tiles: d = j*8 .. j*8+7
            const float t0 = tsb[j * 8 + 2 * t4];
            const float t1 = tsb[j * 8 + 2 * t4 + 1];
            float cA0 = -t0, cA1 = -t1, cA2 = -t0, cA3 = -t1;
            float cB0 = -t0, cB1 = -t1, cB2 = -t0, cB3 = -t1;
            #pragma unroll
            for (int es = 0; es < 4; ++es) {
                const int e0 = es * 16 + 2 * t4;
                const unsigned b0 = *(const unsigned*)&Wk[(j * 8 + g) * SW + e0];
                const unsigned b1 = *(const unsigned*)&Wk[(j * 8 + g) * SW + e0 + 8];
                asm volatile(
                    "mma.sync.aligned.m16n8k16.row.col.f32.bf16.bf16.f32 "
                    "{%0,%1,%2,%3}, {%4,%5,%6,%7}, {%8,%9}, {%0,%1,%2,%3};\n"
                    : "+f"(cA0), "+f"(cA1), "+f"(cA2), "+f"(cA3)
                    : "r"(aA[es][0]), "r"(aA[es][1]), "r"(aA[es][2]), "r"(aA[es][3]),
                      "r"(b0), "r"(b1));
                asm volatile(
                    "mma.sync.aligned.m16n8k16.row.col.f32.bf16.bf16.f32 "
                    "{%0,%1,%2,%3}, {%4,%5,%6,%7}, {%8,%9}, {%0,%1,%2,%3};\n"
                    : "+f"(cB0), "+f"(cB1), "+f"(cB2), "+f"(cB3)
                    : "r"(aB[es][0]), "r"(aB[es][1]), "r"(aB[es][2]), "r"(aB[es][3]),
                      "r"(b0), "r"(b1));
            }
            acc = fmaf(pA0, fmaf(cA0, cA0, cA1 * cA1), acc);
            acc = fmaf(pA8, fmaf(cA2, cA2, cA3 * cA3), acc);
            acc = fmaf(pB0, fmaf(cB0, cB0, cB1 * cB1), acc);
            acc = fmaf(pB8, fmaf(cB2, cB2, cB3 * cB3), acc);
        }
    }
    acc *= -0.5f;

    // constant + logdet part: one thread per batch row
    {
        float c = 0.f;
        #pragma unroll
        for (int kk = 0; kk < 32; ++kk) c = fmaf(Ps[tid * 33 + kk], nhc[kk], c);
        acc += c;
    }

    // deterministic block reduction
    red[tid] = acc;
    __syncthreads();
    #pragma unroll
    for (int st = 128; st > 0; st >>= 1) {
        if (tid < st) red[tid] += red[tid + st];
        __syncthreads();
    }
    if (tid == 0) g_part[blockIdx.x] = red[0];
}

// ---------------- final reduce ----------------
__global__ void __launch_bounds__(1024) reduce_kernel(float* __restrict__ out, int nb)
{
    __shared__ float s[1024];
    const int t = threadIdx.x;
    float a = 0.f;
    for (int i = t; i < nb; i += 1024) a += g_part[i];
    s[t] = a;
    __syncthreads();
    #pragma unroll
    for (int st = 512; st > 0; st >>= 1) {
        if (t < st) s[t] += s[t + st];
        __syncthreads();
    }
    if (t == 0) out[0] = fabsf(s[0]);
}

// ---------------- launch ----------------
extern "C" void kernel_launch(void* const* d_in, const int* in_sizes, int n_in,
                              void* d_out, int out_size)
{
    const float* emb    = (const float*)d_in[0];   // (500000, 64)
    const float* cen    = (const float*)d_in[1];   // (32, 64)
    const float* cov    = (const float*)d_in[2];   // (32, 64, 64)
    const float* pi     = (const float*)d_in[3];   // (500000, 32)
    const int*   labels = (const int*)d_in[4];     // (B,)
    const int B  = in_sizes[4];
    const int nb = B / 256;

    static int configured = 0;
    if (!configured) {
        cudaFuncSetAttribute(main_kernel, cudaFuncAttributeMaxDynamicSharedMemorySize,
                             SMEM_TOTAL);
        configured = 1;
    }

    prep_kernel<<<32, 256>>>(cov, cen);
    main_kernel<<<nb, 256, SMEM_TOTAL>>>(emb, pi, labels);
    reduce_kernel<<<1, 1024>>>((float*)d_out, nb);
}